// round 15
// baseline (speedup 1.0000x reference)
#include <cuda_runtime.h>
#include <cuda_fp16.h>
#include <cstdint>
#include <cstddef>

// ---------------------------------------------------------------------------
// Problem constants: B=4, T=2048, C=2048, H=16, S=128 ; M = B*T = 8192
// ---------------------------------------------------------------------------
#define MDIM 8192
#define CD   2048
#define HH   16
#define SSZ  128
#define TTL  2048
#define PCH  32
#define LCH  64

// Scratch (allocation-free: __device__ globals)
__device__ __half g_xp  [(size_t)MDIM * CD];      // x fp16
__device__ __half g_wkvr[(size_t)3 * CD * CD];    // concat(Wk,Wv,Wr) fp16
__device__ __half g_wop [(size_t)CD * CD];        // Wo fp16
__device__ __half g_gp  [(size_t)MDIM * CD];      // gated output fp16
__device__ __half g_wh  [(size_t)MDIM * CD];      // w = exp(clamp(k)) fp16
__device__ __half g_vh  [(size_t)MDIM * CD];      // v fp16
__device__ __half g_sh  [(size_t)MDIM * CD];      // sigmoid(r) fp16
__device__ float2 g_st  [4 * HH * PCH * SSZ];     // chunk states (num,den) AoS

// ---------------------------------------------------------------------------
// helpers
// ---------------------------------------------------------------------------
__device__ __forceinline__ uint32_t smem_u32(const void* p) {
    uint32_t a;
    asm("{ .reg .u64 t; cvta.to.shared.u64 t, %1; cvt.u32.u64 %0, t; }"
        : "=r"(a) : "l"(p));
    return a;
}
__device__ __forceinline__ void cp16(uint32_t dst, const void* src) {
    asm volatile("cp.async.cg.shared.global [%0], [%1], 16;"
                 :: "r"(dst), "l"(src) : "memory");
}
#define CP_COMMIT() asm volatile("cp.async.commit_group;" ::: "memory")
#define CP_WAIT(n)  asm volatile("cp.async.wait_group %0;" :: "n"(n) : "memory")

#define LDSM4(r0, r1, r2, r3, addr)                                        \
    asm volatile("ldmatrix.sync.aligned.m8n8.x4.shared.b16 "               \
                 "{%0,%1,%2,%3}, [%4];"                                    \
                 : "=r"(r0), "=r"(r1), "=r"(r2), "=r"(r3) : "r"(addr))

#define MMA_F16(d, a, b)                                                   \
    asm volatile(                                                          \
        "mma.sync.aligned.m16n8k16.row.col.f32.f16.f16.f32 "               \
        "{%0,%1,%2,%3}, {%4,%5,%6,%7}, {%8,%9}, {%0,%1,%2,%3};"            \
        : "+f"(d[0]), "+f"(d[1]), "+f"(d[2]), "+f"(d[3])                   \
        : "r"(a[0]), "r"(a[1]), "r"(a[2]), "r"(a[3]), "r"(b[0]), "r"(b[1]))

// ---------------------------------------------------------------------------
// pack-all: x + 4 weights -> fp16, one launch, 4 independent 16B loads/thread
// ---------------------------------------------------------------------------
#define NX4 ((long)MDIM * CD / 4)
#define NW4 ((long)CD * CD / 4)
#define NALL4 (NX4 + 4 * NW4)
#define PACK_PER_T 4

__device__ __forceinline__ void pack_one(long i,
    const float* __restrict__ x,  const float* __restrict__ Wk,
    const float* __restrict__ Wv, const float* __restrict__ Wr,
    const float* __restrict__ Wo,
    __half* __restrict__ xp, __half* __restrict__ wkvr, __half* __restrict__ wop)
{
    const float* src;
    __half* dst;
    long j;
    if (i < NX4) {
        src = x; dst = xp; j = i;
    } else {
        long i2 = i - NX4;
        int  w  = (int)(i2 / NW4);
        j = i2 - (long)w * NW4;
        if      (w == 0) { src = Wk; dst = wkvr; }
        else if (w == 1) { src = Wv; dst = wkvr + (size_t)CD * CD; }
        else if (w == 2) { src = Wr; dst = wkvr + (size_t)2 * CD * CD; }
        else             { src = Wo; dst = wop; }
    }
    float4 f = ((const float4*)src)[j];
    __half2* d = (__half2*)dst + 2 * j;
    d[0] = __floats2half2_rn(f.x, f.y);
    d[1] = __floats2half2_rn(f.z, f.w);
}

__global__ __launch_bounds__(256) void pack_all(
    const float* __restrict__ x,  const float* __restrict__ Wk,
    const float* __restrict__ Wv, const float* __restrict__ Wr,
    const float* __restrict__ Wo,
    __half* __restrict__ xp, __half* __restrict__ wkvr, __half* __restrict__ wop)
{
    const long stride = (long)gridDim.x * blockDim.x;
    long i = (long)blockIdx.x * blockDim.x + threadIdx.x;
#pragma unroll
    for (int u = 0; u < PACK_PER_T; u++) {
        if (i < NALL4)
            pack_one(i, x, Wk, Wv, Wr, Wo, xp, wkvr, wop);
        i += stride;
    }
}

// ---------------------------------------------------------------------------
// FP16 tensor GEMM: C = A[M,K] @ B[N,K]^T, fp16 in.
// Block 128x128x32, 128 threads = 4 warps (2M x 2N), warp tile 64x64.
// 3-stage cp.async pipeline (R6 cadence), per-ks LDSM, 2 CTA/SM.
// Per ks: 8 LDSM.x4 -> 64 MMA (4:1 ratio).
// Plain mode (nsplit==0): f32 -> C0.
// Split mode: block 0 -> w = exp(clamp(k)) [* exp(tf) at t==0] fp16;
//             block 1 -> v fp16;  block 2 -> sigmoid(r) fp16.
// ---------------------------------------------------------------------------
#define LDH 40
#define BUFB (128 * LDH * 2)
#define SMEM_GEMM (6 * BUFB)

__global__ __launch_bounds__(128, 2) void gemm_nt_h(
    const __half* __restrict__ A, const __half* __restrict__ B,
    float* __restrict__ C0,
    __half* __restrict__ Chw, __half* __restrict__ Chv, __half* __restrict__ Chs,
    const float* __restrict__ tf,
    int K, int nsplit)
{
    extern __shared__ __align__(16) char dyn_smem[];
    const uint32_t sA = smem_u32(dyn_smem);
    const uint32_t sB = sA + 3 * BUFB;

    const int tid  = threadIdx.x;
    const int lane = tid & 31;
    const int wid  = tid >> 5;            // 0..3
    const int wm   = (wid & 1) * 64;
    const int wn   = (wid >> 1) * 64;
    const int g    = lane >> 2;
    const int t4   = lane & 3;

    // loader: 128 threads cover 128 rows x 4 chunks per operand per stage
    const int lr = tid >> 2;              // 0..31
    const int lu = tid & 3;               // 0..3
    const __half* Ap = A + (size_t)(blockIdx.y * 128 + lr) * K + lu * 8;
    const __half* Bp = B + (size_t)(blockIdx.x * 128 + lr) * K + lu * 8;
    const uint32_t da = sA + lr * 80 + lu * 16;
    const uint32_t db = sB + lr * 80 + lu * 16;

    const uint32_t a_base = sA + ((wm + (lane & 15)) * LDH + ((lane >> 4) << 3)) * 2;
    const uint32_t b_base = sB + ((wn + (lane & 7) + ((lane >> 4) & 1) * 8) * LDH
                                  + (((lane >> 3) & 1) << 3)) * 2;

    float acc[4][8][4];
#pragma unroll
    for (int mi = 0; mi < 4; mi++)
#pragma unroll
        for (int ni = 0; ni < 8; ni++)
#pragma unroll
            for (int j = 0; j < 4; j++) acc[mi][ni][j] = 0.f;

    const int KT = K / 32;   // 64

#pragma unroll
    for (int pf = 0; pf < 2; pf++) {
        const uint32_t o = (uint32_t)(pf * BUFB);
        const int koff = pf * 32;
#pragma unroll
        for (int rr = 0; rr < 4; rr++) {
            cp16(da + o + rr * (32 * 80), Ap + (size_t)(rr * 32) * K + koff);
            cp16(db + o + rr * (32 * 80), Bp + (size_t)(rr * 32) * K + koff);
        }
        CP_COMMIT();
    }

    int st = 0;
    for (int kt = 0; kt < KT; kt++) {
        if (kt + 1 < KT) { CP_WAIT(1); } else { CP_WAIT(0); }
        __syncthreads();

        const uint32_t so = (uint32_t)(st * BUFB);
#pragma unroll
        for (int ks = 0; ks < 2; ks++) {
            const uint32_t ko = ks * 32;
            uint32_t af[4][4];
            uint32_t bf[8][2];
#pragma unroll
            for (int mi = 0; mi < 4; mi++)
                LDSM4(af[mi][0], af[mi][1], af[mi][2], af[mi][3],
                      a_base + so + mi * (16 * 80) + ko);
#pragma unroll
            for (int pr = 0; pr < 4; pr++)
                LDSM4(bf[2 * pr][0], bf[2 * pr][1], bf[2 * pr + 1][0], bf[2 * pr + 1][1],
                      b_base + so + pr * (16 * 80) + ko);
#pragma unroll
            for (int mi = 0; mi < 4; mi++)
#pragma unroll
                for (int ni = 0; ni < 8; ni++)
                    MMA_F16(acc[mi][ni], af[mi], bf[ni]);
        }

        if (kt + 2 < KT) {
            const int ns = (st + 2 > 2) ? (st - 1) : (st + 2);
            const uint32_t o = (uint32_t)(ns * BUFB);
            const int koff = (kt + 2) * 32;
#pragma unroll
            for (int rr = 0; rr < 4; rr++) {
                cp16(da + o + rr * (32 * 80), Ap + (size_t)(rr * 32) * K + koff);
                cp16(db + o + rr * (32 * 80), Bp + (size_t)(rr * 32) * K + koff);
            }
            CP_COMMIT();
        }
        st = (st + 1 > 2) ? 0 : (st + 1);
    }

    // epilogue
    if (nsplit == 0) {
#pragma unroll
        for (int mi = 0; mi < 4; mi++) {
#pragma unroll
            for (int ni = 0; ni < 8; ni++) {
                const int row = blockIdx.y * 128 + wm + mi * 16 + g;
                const int col = blockIdx.x * 128 + wn + ni * 8 + 2 * t4;
                *(float2*)&C0[(size_t)row * CD + col] =
                    make_float2(acc[mi][ni][0], acc[mi][ni][1]);
                *(float2*)&C0[(size_t)(row + 8) * CD + col] =
                    make_float2(acc[mi][ni][2], acc[mi][ni][3]);
            }
        }
    } else {
        const int which = blockIdx.x / nsplit;
        const int cbx   = blockIdx.x - which * nsplit;
        __half* Ch = (which == 0) ? Chw : ((which == 1) ? Chv : Chs);
#pragma unroll
        for (int mi = 0; mi < 4; mi++) {
#pragma unroll
            for (int ni = 0; ni < 8; ni++) {
                const int row = blockIdx.y * 128 + wm + mi * 16 + g;
                const int col = cbx * 128 + wn + ni * 8 + 2 * t4;
                float a0 = acc[mi][ni][0], a1 = acc[mi][ni][1];
                float a2 = acc[mi][ni][2], a3 = acc[mi][ni][3];
                if (which == 0) {
                    a0 = __expf(fminf(fmaxf(a0, -10.f), 10.f));
                    a1 = __expf(fminf(fmaxf(a1, -10.f), 10.f));
                    a2 = __expf(fminf(fmaxf(a2, -10.f), 10.f));
                    a3 = __expf(fminf(fmaxf(a3, -10.f), 10.f));
                    if ((row & (TTL - 1)) == 0) {
                        a0 *= __expf(tf[col]);
                        a1 *= __expf(tf[col + 1]);
                    }
                    if (((row + 8) & (TTL - 1)) == 0) {
                        a2 *= __expf(tf[col]);
                        a3 *= __expf(tf[col + 1]);
                    }
                } else if (which == 2) {
                    a0 = __fdividef(1.f, 1.f + __expf(-a0));
                    a1 = __fdividef(1.f, 1.f + __expf(-a1));
                    a2 = __fdividef(1.f, 1.f + __expf(-a2));
                    a3 = __fdividef(1.f, 1.f + __expf(-a3));
                }
                *(__half2*)&Ch[(size_t)row * CD + col]       = __floats2half2_rn(a0, a1);
                *(__half2*)&Ch[(size_t)(row + 8) * CD + col] = __floats2half2_rn(a2, a3);
            }
        }
    }
}

// ---------------------------------------------------------------------------
// WKV chunk-parallel scan. w precomputed fp16 (first-token folded), v fp16,
// sigmoid(r) fp16. Inner chain: pure fma.
// ---------------------------------------------------------------------------
__global__ __launch_bounds__(128) void wkv_p1(
    const __half* __restrict__ wv, const __half* __restrict__ v,
    const float* __restrict__ td)
{
    const int s = threadIdx.x, p = blockIdx.x, h = blockIdx.y, b = blockIdx.z;
    const float decay = expf(-expf(td[h * SSZ + s]));
    size_t base = ((size_t)(b * TTL + p * LCH)) * CD + h * SSZ + s;
    float num = 0.f, den = 0.f;
#pragma unroll 8
    for (int i = 0; i < LCH; i++) {
        float w  = __half2float(wv[base]);
        float vv = __half2float(v[base]);
        num = fmaf(decay, num, w * vv);
        den = fmaf(decay, den, w);
        base += CD;
    }
    g_st[(((size_t)b * HH + h) * PCH + p) * SSZ + s] = make_float2(num, den);
}

__global__ __launch_bounds__(128) void wkv_p2(const float* __restrict__ td)
{
    const int s = threadIdx.x, h = blockIdx.x, b = blockIdx.y;
    const float dC = expf(-(float)LCH * expf(td[h * SSZ + s]));
    float2 run = make_float2(0.f, 0.f);
    size_t base = ((size_t)b * HH + h) * PCH;
    for (int p = 0; p < PCH; p++) {
        size_t idx = (base + p) * SSZ + s;
        float2 cur = g_st[idx];
        g_st[idx]  = run;
        run.x = fmaf(dC, run.x, cur.x);
        run.y = fmaf(dC, run.y, cur.y);
    }
}

__global__ __launch_bounds__(128) void wkv_p3(
    const __half* __restrict__ wv, const __half* __restrict__ v,
    const __half* __restrict__ sg, const float* __restrict__ td)
{
    const int s = threadIdx.x, p = blockIdx.x, h = blockIdx.y, b = blockIdx.z;
    const float decay = expf(-expf(td[h * SSZ + s]));
    float2 st = g_st[(((size_t)b * HH + h) * PCH + p) * SSZ + s];
    float num = st.x, den = st.y;
    size_t base = ((size_t)(b * TTL + p * LCH)) * CD + h * SSZ + s;
#pragma unroll 8
    for (int i = 0; i < LCH; i++) {
        float w  = __half2float(wv[base]);
        float vv = __half2float(v[base]);
        num = fmaf(decay, num, w * vv);
        den = fmaf(decay, den, w);
        float sig = __half2float(sg[base]);
        g_gp[base] = __float2half_rn(sig * __fdividef(num, den + 1e-6f));
        base += CD;
    }
}

// ---------------------------------------------------------------------------
extern "C" void kernel_launch(void* const* d_in, const int* in_sizes, int n_in,
                              void* d_out, int out_size)
{
    const float* x  = (const float*)d_in[0];
    const float* Wk = (const float*)d_in[1];
    const float* Wv = (const float*)d_in[2];
    const float* Wr = (const float*)d_in[3];
    const float* Wo = (const float*)d_in[4];
    const float* td = (const float*)d_in[5];
    const float* tf = (const float*)d_in[6];
    float* out = (float*)d_out;

    __half *xp, *wkvr, *wop, *gp, *wh, *vh, *sh;
    cudaGetSymbolAddress((void**)&xp,   g_xp);
    cudaGetSymbolAddress((void**)&wkvr, g_wkvr);
    cudaGetSymbolAddress((void**)&wop,  g_wop);
    cudaGetSymbolAddress((void**)&gp,   g_gp);
    cudaGetSymbolAddress((void**)&wh,   g_wh);
    cudaGetSymbolAddress((void**)&vh,   g_vh);
    cudaGetSymbolAddress((void**)&sh,   g_sh);

    cudaFuncSetAttribute(gemm_nt_h, cudaFuncAttributeMaxDynamicSharedMemorySize,
                         SMEM_GEMM);

    const long nThreads = (NALL4 + PACK_PER_T - 1) / PACK_PER_T;
    pack_all<<<(unsigned)((nThreads + 255) / 256), 256>>>(
        x, Wk, Wv, Wr, Wo, xp, wkvr, wop);

    // fused k/v/r GEMM: k -> w fp16, v -> fp16, r -> sigmoid fp16
    dim3 gridF(3 * CD / 128, MDIM / 128);   // (48, 64)
    gemm_nt_h<<<gridF, 128, SMEM_GEMM>>>(xp, wkvr, nullptr, wh, vh, sh, tf,
                                         CD, CD / 128);

    wkv_p1<<<dim3(PCH, HH, 4), 128>>>(wh, vh, td);
    wkv_p2<<<dim3(HH, 4), 128>>>(td);
    wkv_p3<<<dim3(PCH, HH, 4), 128>>>(wh, vh, sh, td);

    // output GEMM (f32 out)
    dim3 gridO(CD / 128, MDIM / 128);       // (16, 64)
    gemm_nt_h<<<gridO, 128, SMEM_GEMM>>>(gp, wop, out, nullptr, nullptr, nullptr,
                                         nullptr, CD, 0);
}

// round 16
// speedup vs baseline: 1.0710x; 1.0710x over previous
#include <cuda_runtime.h>
#include <cuda_fp16.h>
#include <cstdint>
#include <cstddef>

// ---------------------------------------------------------------------------
// Problem constants: B=4, T=2048, C=2048, H=16, S=128 ; M = B*T = 8192
// ---------------------------------------------------------------------------
#define MDIM 8192
#define CD   2048
#define HH   16
#define SSZ  128
#define TTL  2048
#define PCH  64          // time chunks (parallel)
#define LCH  32          // chunk length (PCH*LCH = TTL)

// Scratch (allocation-free: __device__ globals)
__device__ __half g_xp  [(size_t)MDIM * CD];      // x fp16
__device__ __half g_wkvr[(size_t)3 * CD * CD];    // concat(Wk,Wv,Wr) fp16
__device__ __half g_wop [(size_t)CD * CD];        // Wo fp16
__device__ __half g_gp  [(size_t)MDIM * CD];      // gated output fp16
__device__ __half g_wh  [(size_t)MDIM * CD];      // w = exp(clamp(k)) fp16
__device__ __half g_vh  [(size_t)MDIM * CD];      // v fp16
__device__ __half g_sh  [(size_t)MDIM * CD];      // sigmoid(r) fp16
__device__ float2 g_st  [4 * HH * PCH * SSZ];     // chunk states (num,den) AoS

// ---------------------------------------------------------------------------
// helpers
// ---------------------------------------------------------------------------
__device__ __forceinline__ uint32_t smem_u32(const void* p) {
    uint32_t a;
    asm("{ .reg .u64 t; cvta.to.shared.u64 t, %1; cvt.u32.u64 %0, t; }"
        : "=r"(a) : "l"(p));
    return a;
}
__device__ __forceinline__ void cp16(uint32_t dst, const void* src) {
    asm volatile("cp.async.cg.shared.global [%0], [%1], 16;"
                 :: "r"(dst), "l"(src) : "memory");
}
#define CP_COMMIT() asm volatile("cp.async.commit_group;" ::: "memory")
#define CP_WAIT(n)  asm volatile("cp.async.wait_group %0;" :: "n"(n) : "memory")

#define LDSM4(r0, r1, r2, r3, addr)                                        \
    asm volatile("ldmatrix.sync.aligned.m8n8.x4.shared.b16 "               \
                 "{%0,%1,%2,%3}, [%4];"                                    \
                 : "=r"(r0), "=r"(r1), "=r"(r2), "=r"(r3) : "r"(addr))

#define MMA_F16(d, a, b)                                                   \
    asm volatile(                                                          \
        "mma.sync.aligned.m16n8k16.row.col.f32.f16.f16.f32 "               \
        "{%0,%1,%2,%3}, {%4,%5,%6,%7}, {%8,%9}, {%0,%1,%2,%3};"            \
        : "+f"(d[0]), "+f"(d[1]), "+f"(d[2]), "+f"(d[3])                   \
        : "r"(a[0]), "r"(a[1]), "r"(a[2]), "r"(a[3]), "r"(b[0]), "r"(b[1]))

// ---------------------------------------------------------------------------
// pack-all: x + 4 weights -> fp16, one launch, 4 independent 16B loads/thread
// ---------------------------------------------------------------------------
#define NX4 ((long)MDIM * CD / 4)
#define NW4 ((long)CD * CD / 4)
#define NALL4 (NX4 + 4 * NW4)
#define PACK_PER_T 4

__device__ __forceinline__ void pack_one(long i,
    const float* __restrict__ x,  const float* __restrict__ Wk,
    const float* __restrict__ Wv, const float* __restrict__ Wr,
    const float* __restrict__ Wo,
    __half* __restrict__ xp, __half* __restrict__ wkvr, __half* __restrict__ wop)
{
    const float* src;
    __half* dst;
    long j;
    if (i < NX4) {
        src = x; dst = xp; j = i;
    } else {
        long i2 = i - NX4;
        int  w  = (int)(i2 / NW4);
        j = i2 - (long)w * NW4;
        if      (w == 0) { src = Wk; dst = wkvr; }
        else if (w == 1) { src = Wv; dst = wkvr + (size_t)CD * CD; }
        else if (w == 2) { src = Wr; dst = wkvr + (size_t)2 * CD * CD; }
        else             { src = Wo; dst = wop; }
    }
    float4 f = ((const float4*)src)[j];
    __half2* d = (__half2*)dst + 2 * j;
    d[0] = __floats2half2_rn(f.x, f.y);
    d[1] = __floats2half2_rn(f.z, f.w);
}

__global__ __launch_bounds__(256) void pack_all(
    const float* __restrict__ x,  const float* __restrict__ Wk,
    const float* __restrict__ Wv, const float* __restrict__ Wr,
    const float* __restrict__ Wo,
    __half* __restrict__ xp, __half* __restrict__ wkvr, __half* __restrict__ wop)
{
    const long stride = (long)gridDim.x * blockDim.x;
    long i = (long)blockIdx.x * blockDim.x + threadIdx.x;
#pragma unroll
    for (int u = 0; u < PACK_PER_T; u++) {
        if (i < NALL4)
            pack_one(i, x, Wk, Wv, Wr, Wo, xp, wkvr, wop);
        i += stride;
    }
}

// ---------------------------------------------------------------------------
// FP16 tensor GEMM (R6/R14-proven, FROZEN): C = A[M,K] @ B[N,K]^T.
// Block 128x128x32, 256 thr = 8 warps (2M x 4N), 3-stage cp.async, 2 CTA/SM.
// Plain mode (nsplit==0): f32 -> C0.
// Split mode: block 0 -> w = exp(clamp(k)) [* exp(tf) at t==0] fp16;
//             block 1 -> v fp16;  block 2 -> sigmoid(r) fp16.
// ---------------------------------------------------------------------------
#define LDH 40
#define BUFB (128 * LDH * 2)
#define SMEM_GEMM (6 * BUFB)

__global__ __launch_bounds__(256, 2) void gemm_nt_h(
    const __half* __restrict__ A, const __half* __restrict__ B,
    float* __restrict__ C0,
    __half* __restrict__ Chw, __half* __restrict__ Chv, __half* __restrict__ Chs,
    const float* __restrict__ tf,
    int K, int nsplit)
{
    extern __shared__ __align__(16) char dyn_smem[];
    const uint32_t sA = smem_u32(dyn_smem);
    const uint32_t sB = sA + 3 * BUFB;

    const int tid  = threadIdx.x;
    const int lane = tid & 31;
    const int wid  = tid >> 5;
    const int wm   = (wid & 1) * 64;
    const int wn   = (wid >> 1) * 32;
    const int g    = lane >> 2;
    const int t4   = lane & 3;

    const int lr = tid >> 2;
    const int lu = tid & 3;
    const __half* Ap0 = A + (size_t)(blockIdx.y * 128 + lr) * K + lu * 8;
    const __half* Ap1 = Ap0 + (size_t)64 * K;
    const __half* Bp0 = B + (size_t)(blockIdx.x * 128 + lr) * K + lu * 8;
    const __half* Bp1 = Bp0 + (size_t)64 * K;
    const uint32_t da0 = sA + lr * 80 + lu * 16, da1 = da0 + 64 * 80;
    const uint32_t db0 = sB + lr * 80 + lu * 16, db1 = db0 + 64 * 80;

    const uint32_t a_base = sA + ((wm + (lane & 15)) * LDH + ((lane >> 4) << 3)) * 2;
    const uint32_t b_base = sB + ((wn + (lane & 7) + ((lane >> 4) & 1) * 8) * LDH
                                  + (((lane >> 3) & 1) << 3)) * 2;

    float acc[4][4][4];
#pragma unroll
    for (int mi = 0; mi < 4; mi++)
#pragma unroll
        for (int ni = 0; ni < 4; ni++)
#pragma unroll
            for (int j = 0; j < 4; j++) acc[mi][ni][j] = 0.f;

    const int KT = K / 32;   // 64

#pragma unroll
    for (int pf = 0; pf < 2; pf++) {
        const uint32_t o = (uint32_t)(pf * BUFB);
        const int koff = pf * 32;
        cp16(da0 + o, Ap0 + koff); cp16(da1 + o, Ap1 + koff);
        cp16(db0 + o, Bp0 + koff); cp16(db1 + o, Bp1 + koff);
        CP_COMMIT();
    }

    int st = 0;
    for (int kt = 0; kt < KT; kt++) {
        if (kt + 1 < KT) { CP_WAIT(1); } else { CP_WAIT(0); }
        __syncthreads();

        const uint32_t so = (uint32_t)(st * BUFB);
#pragma unroll
        for (int ks = 0; ks < 2; ks++) {
            const uint32_t ko = ks * 32;
            uint32_t af[4][4];
            uint32_t bf[4][2];
#pragma unroll
            for (int mi = 0; mi < 4; mi++)
                LDSM4(af[mi][0], af[mi][1], af[mi][2], af[mi][3],
                      a_base + so + mi * (16 * 80) + ko);
#pragma unroll
            for (int pr = 0; pr < 2; pr++)
                LDSM4(bf[2 * pr][0], bf[2 * pr][1], bf[2 * pr + 1][0], bf[2 * pr + 1][1],
                      b_base + so + pr * (16 * 80) + ko);
#pragma unroll
            for (int mi = 0; mi < 4; mi++)
#pragma unroll
                for (int ni = 0; ni < 4; ni++)
                    MMA_F16(acc[mi][ni], af[mi], bf[ni]);
        }

        if (kt + 2 < KT) {
            const int ns = (st + 2 > 2) ? (st - 1) : (st + 2);
            const uint32_t o = (uint32_t)(ns * BUFB);
            const int koff = (kt + 2) * 32;
            cp16(da0 + o, Ap0 + koff); cp16(da1 + o, Ap1 + koff);
            cp16(db0 + o, Bp0 + koff); cp16(db1 + o, Bp1 + koff);
            CP_COMMIT();
        }
        st = (st + 1 > 2) ? 0 : (st + 1);
    }

    // epilogue
    if (nsplit == 0) {
#pragma unroll
        for (int mi = 0; mi < 4; mi++) {
#pragma unroll
            for (int ni = 0; ni < 4; ni++) {
                const int row = blockIdx.y * 128 + wm + mi * 16 + g;
                const int col = blockIdx.x * 128 + wn + ni * 8 + 2 * t4;
                *(float2*)&C0[(size_t)row * CD + col] =
                    make_float2(acc[mi][ni][0], acc[mi][ni][1]);
                *(float2*)&C0[(size_t)(row + 8) * CD + col] =
                    make_float2(acc[mi][ni][2], acc[mi][ni][3]);
            }
        }
    } else {
        const int which = blockIdx.x / nsplit;
        const int cbx   = blockIdx.x - which * nsplit;
        __half* Ch = (which == 0) ? Chw : ((which == 1) ? Chv : Chs);
#pragma unroll
        for (int mi = 0; mi < 4; mi++) {
#pragma unroll
            for (int ni = 0; ni < 4; ni++) {
                const int row = blockIdx.y * 128 + wm + mi * 16 + g;
                const int col = cbx * 128 + wn + ni * 8 + 2 * t4;
                float a0 = acc[mi][ni][0], a1 = acc[mi][ni][1];
                float a2 = acc[mi][ni][2], a3 = acc[mi][ni][3];
                if (which == 0) {
                    a0 = __expf(fminf(fmaxf(a0, -10.f), 10.f));
                    a1 = __expf(fminf(fmaxf(a1, -10.f), 10.f));
                    a2 = __expf(fminf(fmaxf(a2, -10.f), 10.f));
                    a3 = __expf(fminf(fmaxf(a3, -10.f), 10.f));
                    if ((row & (TTL - 1)) == 0) {
                        a0 *= __expf(tf[col]);
                        a1 *= __expf(tf[col + 1]);
                    }
                    if (((row + 8) & (TTL - 1)) == 0) {
                        a2 *= __expf(tf[col]);
                        a3 *= __expf(tf[col + 1]);
                    }
                } else if (which == 2) {
                    a0 = __fdividef(1.f, 1.f + __expf(-a0));
                    a1 = __fdividef(1.f, 1.f + __expf(-a1));
                    a2 = __fdividef(1.f, 1.f + __expf(-a2));
                    a3 = __fdividef(1.f, 1.f + __expf(-a3));
                }
                *(__half2*)&Ch[(size_t)row * CD + col]       = __floats2half2_rn(a0, a1);
                *(__half2*)&Ch[(size_t)(row + 8) * CD + col] = __floats2half2_rn(a2, a3);
            }
        }
    }
}

// ---------------------------------------------------------------------------
// WKV chunk-parallel scan: PCH=64 chunks of LCH=32; 2 channels/thread (half2).
// p1/p3 grid (PCH, HH/2, B): block = 128 thr = 256 channels = 2 heads.
// State stays AoS float2 (R8 lesson); pair (s, s+1) accessed as one float4.
// ---------------------------------------------------------------------------
__global__ __launch_bounds__(128) void wkv_p1(
    const __half* __restrict__ wv, const __half* __restrict__ v,
    const float* __restrict__ td)
{
    const int t = threadIdx.x, p = blockIdx.x, hg = blockIdx.y, b = blockIdx.z;
    const int c2 = hg * 256 + t * 2;
    const float dec0 = expf(-expf(td[c2]));
    const float dec1 = expf(-expf(td[c2 + 1]));
    size_t base = ((size_t)(b * TTL + p * LCH)) * CD + c2;
    float n0 = 0.f, n1 = 0.f, d0 = 0.f, d1 = 0.f;
#pragma unroll 8
    for (int i = 0; i < LCH; i++) {
        __half2 w2 = *(const __half2*)&wv[base];
        __half2 v2 = *(const __half2*)&v[base];
        float w0 = __low2float(w2), w1 = __high2float(w2);
        float v0 = __low2float(v2), v1 = __high2float(v2);
        n0 = fmaf(dec0, n0, w0 * v0);
        n1 = fmaf(dec1, n1, w1 * v1);
        d0 = fmaf(dec0, d0, w0);
        d1 = fmaf(dec1, d1, w1);
        base += CD;
    }
    const size_t idx = (((size_t)b * HH + (c2 >> 7)) * PCH + p) * SSZ + (c2 & 127);
    *(float4*)&g_st[idx] = make_float4(n0, d0, n1, d1);
}

__global__ __launch_bounds__(128) void wkv_p2(const float* __restrict__ td)
{
    const int s = threadIdx.x, h = blockIdx.x, b = blockIdx.y;
    const float dC = expf(-(float)LCH * expf(td[h * SSZ + s]));
    float2 run = make_float2(0.f, 0.f);
    size_t base = ((size_t)b * HH + h) * PCH;
    for (int p = 0; p < PCH; p++) {
        size_t idx = (base + p) * SSZ + s;
        float2 cur = g_st[idx];
        g_st[idx]  = run;
        run.x = fmaf(dC, run.x, cur.x);
        run.y = fmaf(dC, run.y, cur.y);
    }
}

__global__ __launch_bounds__(128) void wkv_p3(
    const __half* __restrict__ wv, const __half* __restrict__ v,
    const __half* __restrict__ sg, const float* __restrict__ td)
{
    const int t = threadIdx.x, p = blockIdx.x, hg = blockIdx.y, b = blockIdx.z;
    const int c2 = hg * 256 + t * 2;
    const float dec0 = expf(-expf(td[c2]));
    const float dec1 = expf(-expf(td[c2 + 1]));
    const size_t idx = (((size_t)b * HH + (c2 >> 7)) * PCH + p) * SSZ + (c2 & 127);
    float4 st = *(const float4*)&g_st[idx];
    float n0 = st.x, d0 = st.y, n1 = st.z, d1 = st.w;
    size_t base = ((size_t)(b * TTL + p * LCH)) * CD + c2;
#pragma unroll 8
    for (int i = 0; i < LCH; i++) {
        __half2 w2 = *(const __half2*)&wv[base];
        __half2 v2 = *(const __half2*)&v[base];
        __half2 s2 = *(const __half2*)&sg[base];
        float w0 = __low2float(w2), w1 = __high2float(w2);
        float v0 = __low2float(v2), v1 = __high2float(v2);
        n0 = fmaf(dec0, n0, w0 * v0);
        n1 = fmaf(dec1, n1, w1 * v1);
        d0 = fmaf(dec0, d0, w0);
        d1 = fmaf(dec1, d1, w1);
        float o0 = __low2float(s2)  * __fdividef(n0, d0 + 1e-6f);
        float o1 = __high2float(s2) * __fdividef(n1, d1 + 1e-6f);
        *(__half2*)&g_gp[base] = __floats2half2_rn(o0, o1);
        base += CD;
    }
}

// ---------------------------------------------------------------------------
extern "C" void kernel_launch(void* const* d_in, const int* in_sizes, int n_in,
                              void* d_out, int out_size)
{
    const float* x  = (const float*)d_in[0];
    const float* Wk = (const float*)d_in[1];
    const float* Wv = (const float*)d_in[2];
    const float* Wr = (const float*)d_in[3];
    const float* Wo = (const float*)d_in[4];
    const float* td = (const float*)d_in[5];
    const float* tf = (const float*)d_in[6];
    float* out = (float*)d_out;

    __half *xp, *wkvr, *wop, *gp, *wh, *vh, *sh;
    cudaGetSymbolAddress((void**)&xp,   g_xp);
    cudaGetSymbolAddress((void**)&wkvr, g_wkvr);
    cudaGetSymbolAddress((void**)&wop,  g_wop);
    cudaGetSymbolAddress((void**)&gp,   g_gp);
    cudaGetSymbolAddress((void**)&wh,   g_wh);
    cudaGetSymbolAddress((void**)&vh,   g_vh);
    cudaGetSymbolAddress((void**)&sh,   g_sh);

    cudaFuncSetAttribute(gemm_nt_h, cudaFuncAttributeMaxDynamicSharedMemorySize,
                         SMEM_GEMM);

    const long nThreads = (NALL4 + PACK_PER_T - 1) / PACK_PER_T;
    pack_all<<<(unsigned)((nThreads + 255) / 256), 256>>>(
        x, Wk, Wv, Wr, Wo, xp, wkvr, wop);

    // fused k/v/r GEMM: k -> w fp16, v -> fp16, r -> sigmoid fp16
    dim3 gridF(3 * CD / 128, MDIM / 128);   // (48, 64)
    gemm_nt_h<<<gridF, 256, SMEM_GEMM>>>(xp, wkvr, nullptr, wh, vh, sh, tf,
                                         CD, CD / 128);

    wkv_p1<<<dim3(PCH, HH / 2, 4), 128>>>(wh, vh, td);
    wkv_p2<<<dim3(HH, 4), 128>>>(td);
    wkv_p3<<<dim3(PCH, HH / 2, 4), 128>>>(wh, vh, sh, td);

    // output GEMM (f32 out)
    dim3 gridO(CD / 128, MDIM / 128);       // (16, 64)
    gemm_nt_h<<<gridO, 256, SMEM_GEMM>>>(gp, wop, out, nullptr, nullptr, nullptr,
                                         nullptr, CD, 0);
}